// round 3
// baseline (speedup 1.0000x reference)
#include <cuda_runtime.h>

#define NN 100000
#define NE 3200000
#define NG 1000

// ---------------- scratch (device globals; no allocation allowed) ----------------
__device__ __align__(16) float g_q[NN * 32];
__device__ __align__(16) float g_k[NN * 32];
__device__ __align__(16) float g_v[NN * 32];
__device__ __align__(16) float g_skip[NN * 32];
__device__ __align__(16) float g_agg[NN * 32];
__device__ __align__(16) float g_h[NN * 32];
__device__ __align__(16) float g_s[NE];
__device__ float g_smax[NN];
__device__ float g_denom[NN];
__device__ __align__(16) float g_pool[NG * 32];
__device__ float g_cnt[NG];

// ---------------- kernels ----------------

// Fused: q/k/v/skip projections + per-node init of smax/denom/agg.
// FROM_H selects layer-2 input (previous layer output in g_h).
template <int IN, int D, bool FROM_H>
__global__ void node_transform(const float* __restrict__ x,
                               const float* __restrict__ Wq, const float* __restrict__ bq,
                               const float* __restrict__ Wk, const float* __restrict__ bk,
                               const float* __restrict__ Wv, const float* __restrict__ bv,
                               const float* __restrict__ Ws, const float* __restrict__ bs) {
    __shared__ float smem[4 * IN * D + 4 * D];
    float* sWq = smem;
    float* sWk = smem + IN * D;
    float* sWv = smem + 2 * IN * D;
    float* sWs = smem + 3 * IN * D;
    float* sb  = smem + 4 * IN * D;
    for (int i = threadIdx.x; i < IN * D; i += blockDim.x) {
        sWq[i] = Wq[i]; sWk[i] = Wk[i]; sWv[i] = Wv[i]; sWs[i] = Ws[i];
    }
    for (int i = threadIdx.x; i < D; i += blockDim.x) {
        sb[i] = bq[i]; sb[D + i] = bk[i]; sb[2 * D + i] = bv[i]; sb[3 * D + i] = bs[i];
    }
    __syncthreads();

    int n = blockIdx.x * blockDim.x + threadIdx.x;
    if (n >= NN) return;

    const float* xp = FROM_H ? (const float*)g_h : x;
    float xv[IN];
#pragma unroll
    for (int i = 0; i < IN; i++) xv[i] = xp[(size_t)n * IN + i];

    float acc[D];
#pragma unroll
    for (int j = 0; j < D; j++) acc[j] = sb[j];
#pragma unroll
    for (int i = 0; i < IN; i++) {
        float xi = xv[i];
#pragma unroll
        for (int j = 0; j < D; j++) acc[j] += xi * sWq[i * D + j];
    }
#pragma unroll
    for (int j = 0; j < D; j++) g_q[(size_t)n * D + j] = acc[j];

#pragma unroll
    for (int j = 0; j < D; j++) acc[j] = sb[D + j];
#pragma unroll
    for (int i = 0; i < IN; i++) {
        float xi = xv[i];
#pragma unroll
        for (int j = 0; j < D; j++) acc[j] += xi * sWk[i * D + j];
    }
#pragma unroll
    for (int j = 0; j < D; j++) g_k[(size_t)n * D + j] = acc[j];

#pragma unroll
    for (int j = 0; j < D; j++) acc[j] = sb[2 * D + j];
#pragma unroll
    for (int i = 0; i < IN; i++) {
        float xi = xv[i];
#pragma unroll
        for (int j = 0; j < D; j++) acc[j] += xi * sWv[i * D + j];
    }
#pragma unroll
    for (int j = 0; j < D; j++) g_v[(size_t)n * D + j] = acc[j];

#pragma unroll
    for (int j = 0; j < D; j++) acc[j] = sb[3 * D + j];
#pragma unroll
    for (int i = 0; i < IN; i++) {
        float xi = xv[i];
#pragma unroll
        for (int j = 0; j < D; j++) acc[j] += xi * sWs[i * D + j];
    }
#pragma unroll
    for (int j = 0; j < D; j++) g_skip[(size_t)n * D + j] = acc[j];

    g_smax[n] = __int_as_float(0xFF800000);  // -inf
    g_denom[n] = 0.0f;
#pragma unroll
    for (int j = 0; j < D; j++) g_agg[(size_t)n * D + j] = 0.0f;
}

__device__ __forceinline__ void atomicMaxF(float* addr, float v) {
    if (v >= 0.0f)
        atomicMax((int*)addr, __float_as_int(v));
    else
        atomicMin((unsigned int*)addr, (unsigned int)__float_as_int(v));
}

template <int D>
__global__ void edge_score(const int* __restrict__ srcp, const int* __restrict__ dstp) {
    int e = blockIdx.x * blockDim.x + threadIdx.x;
    if (e >= NE) return;
    int s = srcp[e];
    int d = dstp[e];
    const float4* qp = reinterpret_cast<const float4*>(g_q + (size_t)d * D);
    const float4* kp = reinterpret_cast<const float4*>(g_k + (size_t)s * D);
    float acc = 0.0f;
#pragma unroll
    for (int i = 0; i < D / 4; i++) {
        float4 a = qp[i];
        float4 b = kp[i];
        acc += a.x * b.x + a.y * b.y + a.z * b.z + a.w * b.w;
    }
    acc *= (D == 16) ? 0.25f : 0.17677669529663688f;  // 1/sqrt(D)
    g_s[e] = acc;
    atomicMaxF(&g_smax[d], acc);
}

__global__ void edge_exp(const int* __restrict__ dstp) {
    int e = blockIdx.x * blockDim.x + threadIdx.x;
    if (e >= NE) return;
    int d = dstp[e];
    float ev = __expf(g_s[e] - g_smax[d]);
    g_s[e] = ev;
    atomicAdd(&g_denom[d], ev);
}

template <int D>
__global__ void edge_agg(const int* __restrict__ srcp, const int* __restrict__ dstp) {
    int e = blockIdx.x * blockDim.x + threadIdx.x;
    if (e >= NE) return;
    int s = srcp[e];
    int d = dstp[e];
    float alpha = g_s[e] / fmaxf(g_denom[d], 1e-16f);
    const float4* vp = reinterpret_cast<const float4*>(g_v + (size_t)s * D);
    float* ap = g_agg + (size_t)d * D;
#pragma unroll
    for (int i = 0; i < D / 4; i++) {
        float4 v = vp[i];
        asm volatile("red.global.add.v4.f32 [%0], {%1, %2, %3, %4};" ::"l"(ap + i * 4),
                     "f"(alpha * v.x), "f"(alpha * v.y), "f"(alpha * v.z), "f"(alpha * v.w)
                     : "memory");
    }
}

template <int D>
__global__ void epilogue_relu() {
    int n = blockIdx.x * blockDim.x + threadIdx.x;
    if (n >= NN) return;
#pragma unroll
    for (int j = 0; j < D; j++)
        g_h[(size_t)n * D + j] = fmaxf(g_agg[(size_t)n * D + j] + g_skip[(size_t)n * D + j], 0.0f);
}

__global__ void pool_zero() {
    int i = blockIdx.x * blockDim.x + threadIdx.x;
    if (i < NG * 32) g_pool[i] = 0.0f;
    if (i < NG) g_cnt[i] = 0.0f;
}

__global__ void pool(const int* __restrict__ batch) {
    int n = blockIdx.x * blockDim.x + threadIdx.x;
    if (n >= NN) return;
    int g = batch[n];
    const float4* hp = reinterpret_cast<const float4*>(g_h + (size_t)n * 32);
    float* pp = g_pool + (size_t)g * 32;
#pragma unroll
    for (int i = 0; i < 8; i++) {
        float4 h = hp[i];
        asm volatile("red.global.add.v4.f32 [%0], {%1, %2, %3, %4};" ::"l"(pp + i * 4),
                     "f"(h.x), "f"(h.y), "f"(h.z), "f"(h.w)
                     : "memory");
    }
    atomicAdd(&g_cnt[g], 1.0f);
}

__global__ void mlp_head(const float* __restrict__ Wf1, const float* __restrict__ bf1,
                         const float* __restrict__ Wf2, const float* __restrict__ bf2,
                         float* __restrict__ out) {
    int g = blockIdx.x * blockDim.x + threadIdx.x;
    if (g >= NG) return;
    float inv = 1.0f / fmaxf(g_cnt[g], 1.0f);
    float gv[32];
#pragma unroll
    for (int i = 0; i < 32; i++) gv[i] = g_pool[(size_t)g * 32 + i] * inv;
    float o = bf2[0];
    for (int j = 0; j < 64; j++) {
        float h = bf1[j];
#pragma unroll
        for (int i = 0; i < 32; i++) h += gv[i] * Wf1[i * 64 + j];
        o += fmaxf(h, 0.0f) * Wf2[j];
    }
    out[g] = o;
}

// ---------------- launch ----------------

extern "C" void kernel_launch(void* const* d_in, const int* in_sizes, int n_in,
                              void* d_out, int out_size) {
    const float* x     = (const float*)d_in[0];
    const int* ei      = (const int*)d_in[1];   // int32: jax default (x64 disabled)
    const int* batch   = (const int*)d_in[2];
    const float* Wq1 = (const float*)d_in[3];
    const float* bq1 = (const float*)d_in[4];
    const float* Wk1 = (const float*)d_in[5];
    const float* bk1 = (const float*)d_in[6];
    const float* Wv1 = (const float*)d_in[7];
    const float* bv1 = (const float*)d_in[8];
    const float* Ws1 = (const float*)d_in[9];
    const float* bs1 = (const float*)d_in[10];
    const float* Wq2 = (const float*)d_in[11];
    const float* bq2 = (const float*)d_in[12];
    const float* Wk2 = (const float*)d_in[13];
    const float* bk2 = (const float*)d_in[14];
    const float* Wv2 = (const float*)d_in[15];
    const float* bv2 = (const float*)d_in[16];
    const float* Ws2 = (const float*)d_in[17];
    const float* bs2 = (const float*)d_in[18];
    const float* Wf1 = (const float*)d_in[19];
    const float* bf1 = (const float*)d_in[20];
    const float* Wf2 = (const float*)d_in[21];
    const float* bf2 = (const float*)d_in[22];
    float* out = (float*)d_out;

    const int* srcp = ei;
    const int* dstp = ei + NE;

    const int EB = (NE + 255) / 256;
    const int NB = (NN + 255) / 256;

    // Layer 1 (11 -> 16)
    node_transform<11, 16, false><<<NB, 256>>>(x, Wq1, bq1, Wk1, bk1, Wv1, bv1, Ws1, bs1);
    edge_score<16><<<EB, 256>>>(srcp, dstp);
    edge_exp<<<EB, 256>>>(dstp);
    edge_agg<16><<<EB, 256>>>(srcp, dstp);
    epilogue_relu<16><<<NB, 256>>>();

    // Layer 2 (16 -> 32), input read from g_h inside the kernel
    node_transform<16, 32, true><<<NB, 256>>>(nullptr, Wq2, bq2, Wk2, bk2, Wv2, bv2, Ws2, bs2);
    edge_score<32><<<EB, 256>>>(srcp, dstp);
    edge_exp<<<EB, 256>>>(dstp);
    edge_agg<32><<<EB, 256>>>(srcp, dstp);
    epilogue_relu<32><<<NB, 256>>>();

    // Pool + MLP head
    pool_zero<<<(NG * 32 + 255) / 256, 256>>>();
    pool<<<NB, 256>>>(batch);
    mlp_head<<<(NG + 127) / 128, 128>>>(Wf1, bf1, Wf2, bf2, out);
}

// round 4
// speedup vs baseline: 1.0257x; 1.0257x over previous
#include <cuda_runtime.h>

#define NN 100000
#define NE 3200000
#define NG 1000

// ---------------- scratch (device globals; no allocation allowed) ----------------
__device__ __align__(16) float g_q[NN * 32];
__device__ __align__(16) float g_k[NN * 32];
__device__ __align__(16) float g_v[NN * 32];
__device__ __align__(16) float g_skip[NN * 32];
__device__ __align__(16) float g_h[NN * 32];
__device__ int g_cnt[NN];
__device__ int g_off[NN + 1];
__device__ int g_cur[NN];
__device__ __align__(16) int g_csr_src[NE];
__device__ __align__(16) float g_pool[NG * 32];
__device__ float g_gcnt[NG];

// ---------------- CSR build ----------------

__global__ void zero_cnt() {
    int i = blockIdx.x * blockDim.x + threadIdx.x;
    if (i < NN) g_cnt[i] = 0;
}

__global__ void hist(const int* __restrict__ dstp) {
    int e = blockIdx.x * blockDim.x + threadIdx.x;
    if (e < NE) atomicAdd(&g_cnt[dstp[e]], 1);
}

// Single-block exclusive scan over g_cnt -> g_off (and g_cur copy).
__global__ void scan_offsets() {
    const int T = 1024;
    const int CHUNK = (NN + T - 1) / T;  // 98
    __shared__ int s_sums[T];
    int t = threadIdx.x;
    int lo = t * CHUNK;
    int hi = min(lo + CHUNK, NN);
    int s = 0;
    for (int i = lo; i < hi; i++) s += g_cnt[i];
    s_sums[t] = s;
    __syncthreads();
    // Hillis-Steele inclusive scan
    for (int o = 1; o < T; o <<= 1) {
        int v = (t >= o) ? s_sums[t - o] : 0;
        __syncthreads();
        s_sums[t] += v;
        __syncthreads();
    }
    int run = (t == 0) ? 0 : s_sums[t - 1];
    for (int i = lo; i < hi; i++) {
        g_off[i] = run;
        g_cur[i] = run;
        run += g_cnt[i];
    }
    if (t == 0) g_off[NN] = NE;
}

__global__ void scatter(const int* __restrict__ srcp, const int* __restrict__ dstp) {
    int e = blockIdx.x * blockDim.x + threadIdx.x;
    if (e >= NE) return;
    int pos = atomicAdd(&g_cur[dstp[e]], 1);
    g_csr_src[pos] = srcp[e];
}

// ---------------- node transform (q/k/v/skip projections) ----------------

template <int IN, int D, bool FROM_H>
__global__ void node_transform(const float* __restrict__ x,
                               const float* __restrict__ Wq, const float* __restrict__ bq,
                               const float* __restrict__ Wk, const float* __restrict__ bk,
                               const float* __restrict__ Wv, const float* __restrict__ bv,
                               const float* __restrict__ Ws, const float* __restrict__ bs) {
    __shared__ float smem[4 * IN * D + 4 * D];
    float* sWq = smem;
    float* sWk = smem + IN * D;
    float* sWv = smem + 2 * IN * D;
    float* sWs = smem + 3 * IN * D;
    float* sb  = smem + 4 * IN * D;
    for (int i = threadIdx.x; i < IN * D; i += blockDim.x) {
        sWq[i] = Wq[i]; sWk[i] = Wk[i]; sWv[i] = Wv[i]; sWs[i] = Ws[i];
    }
    for (int i = threadIdx.x; i < D; i += blockDim.x) {
        sb[i] = bq[i]; sb[D + i] = bk[i]; sb[2 * D + i] = bv[i]; sb[3 * D + i] = bs[i];
    }
    __syncthreads();

    int n = blockIdx.x * blockDim.x + threadIdx.x;
    if (n >= NN) return;

    const float* xp = FROM_H ? (const float*)g_h : x;
    float xv[IN];
#pragma unroll
    for (int i = 0; i < IN; i++) xv[i] = xp[(size_t)n * IN + i];

    float acc[D];
#pragma unroll
    for (int j = 0; j < D; j++) acc[j] = sb[j];
#pragma unroll
    for (int i = 0; i < IN; i++) {
        float xi = xv[i];
#pragma unroll
        for (int j = 0; j < D; j++) acc[j] += xi * sWq[i * D + j];
    }
#pragma unroll
    for (int j = 0; j < D; j++) g_q[(size_t)n * D + j] = acc[j];

#pragma unroll
    for (int j = 0; j < D; j++) acc[j] = sb[D + j];
#pragma unroll
    for (int i = 0; i < IN; i++) {
        float xi = xv[i];
#pragma unroll
        for (int j = 0; j < D; j++) acc[j] += xi * sWk[i * D + j];
    }
#pragma unroll
    for (int j = 0; j < D; j++) g_k[(size_t)n * D + j] = acc[j];

#pragma unroll
    for (int j = 0; j < D; j++) acc[j] = sb[2 * D + j];
#pragma unroll
    for (int i = 0; i < IN; i++) {
        float xi = xv[i];
#pragma unroll
        for (int j = 0; j < D; j++) acc[j] += xi * sWv[i * D + j];
    }
#pragma unroll
    for (int j = 0; j < D; j++) g_v[(size_t)n * D + j] = acc[j];

#pragma unroll
    for (int j = 0; j < D; j++) acc[j] = sb[3 * D + j];
#pragma unroll
    for (int i = 0; i < IN; i++) {
        float xi = xv[i];
#pragma unroll
        for (int j = 0; j < D; j++) acc[j] += xi * sWs[i * D + j];
    }
#pragma unroll
    for (int j = 0; j < D; j++) g_skip[(size_t)n * D + j] = acc[j];
}

// ---------------- fused attention: warp per dst node, single edge pass ----------------
// alpha = exp(s)/sum(exp(s)) (no max subtraction; scores are small here).
// agg = sum(e*v)/sum(e); h = relu(agg + skip).

template <int D>
__global__ void attn_fused() {
    int gw = (blockIdx.x * blockDim.x + threadIdx.x) >> 5;
    int lane = threadIdx.x & 31;
    if (gw >= NN) return;

    const float scale = (D == 16) ? 0.25f : 0.17677669529663688f;  // 1/sqrt(D)

    // load q[gw] (broadcast across warp; L1-cached)
    float q[D];
    const float4* qp = reinterpret_cast<const float4*>(g_q + (size_t)gw * D);
#pragma unroll
    for (int i = 0; i < D / 4; i++) {
        float4 t = qp[i];
        q[4 * i + 0] = t.x; q[4 * i + 1] = t.y; q[4 * i + 2] = t.z; q[4 * i + 3] = t.w;
    }

    int begin = g_off[gw];
    int end = g_off[gw + 1];

    float acc[D];
#pragma unroll
    for (int j = 0; j < D; j++) acc[j] = 0.0f;
    float den = 0.0f;

    for (int idx = begin + lane; idx < end; idx += 32) {
        int s = g_csr_src[idx];
        const float4* kp = reinterpret_cast<const float4*>(g_k + (size_t)s * D);
        float dot = 0.0f;
#pragma unroll
        for (int i = 0; i < D / 4; i++) {
            float4 kv = kp[i];
            dot += q[4 * i + 0] * kv.x + q[4 * i + 1] * kv.y +
                   q[4 * i + 2] * kv.z + q[4 * i + 3] * kv.w;
        }
        float e = __expf(dot * scale);
        den += e;
        const float4* vp = reinterpret_cast<const float4*>(g_v + (size_t)s * D);
#pragma unroll
        for (int i = 0; i < D / 4; i++) {
            float4 vv = vp[i];
            acc[4 * i + 0] += e * vv.x;
            acc[4 * i + 1] += e * vv.y;
            acc[4 * i + 2] += e * vv.z;
            acc[4 * i + 3] += e * vv.w;
        }
    }

    // butterfly reduce across warp
#pragma unroll
    for (int o = 16; o > 0; o >>= 1) {
        den += __shfl_xor_sync(0xFFFFFFFFu, den, o);
#pragma unroll
        for (int j = 0; j < D; j++) acc[j] += __shfl_xor_sync(0xFFFFFFFFu, acc[j], o);
    }

    if (lane == 0) {
        float inv = 1.0f / fmaxf(den, 1e-16f);
        const float4* skp = reinterpret_cast<const float4*>(g_skip + (size_t)gw * D);
        float4* hp = reinterpret_cast<float4*>(g_h + (size_t)gw * D);
#pragma unroll
        for (int i = 0; i < D / 4; i++) {
            float4 sk = skp[i];
            float4 o;
            o.x = fmaxf(acc[4 * i + 0] * inv + sk.x, 0.0f);
            o.y = fmaxf(acc[4 * i + 1] * inv + sk.y, 0.0f);
            o.z = fmaxf(acc[4 * i + 2] * inv + sk.z, 0.0f);
            o.w = fmaxf(acc[4 * i + 3] * inv + sk.w, 0.0f);
            hp[i] = o;
        }
    }
}

// ---------------- pool + head ----------------

__global__ void pool_zero() {
    int i = blockIdx.x * blockDim.x + threadIdx.x;
    if (i < NG * 32) g_pool[i] = 0.0f;
    if (i < NG) g_gcnt[i] = 0.0f;
}

__global__ void pool(const int* __restrict__ batch) {
    int n = blockIdx.x * blockDim.x + threadIdx.x;
    if (n >= NN) return;
    int g = batch[n];
    const float4* hp = reinterpret_cast<const float4*>(g_h + (size_t)n * 32);
    float* pp = g_pool + (size_t)g * 32;
#pragma unroll
    for (int i = 0; i < 8; i++) {
        float4 h = hp[i];
        asm volatile("red.global.add.v4.f32 [%0], {%1, %2, %3, %4};" ::"l"(pp + i * 4),
                     "f"(h.x), "f"(h.y), "f"(h.z), "f"(h.w)
                     : "memory");
    }
    atomicAdd(&g_gcnt[g], 1.0f);
}

__global__ void mlp_head(const float* __restrict__ Wf1, const float* __restrict__ bf1,
                         const float* __restrict__ Wf2, const float* __restrict__ bf2,
                         float* __restrict__ out) {
    int g = blockIdx.x * blockDim.x + threadIdx.x;
    if (g >= NG) return;
    float inv = 1.0f / fmaxf(g_gcnt[g], 1.0f);
    float gv[32];
#pragma unroll
    for (int i = 0; i < 32; i++) gv[i] = g_pool[(size_t)g * 32 + i] * inv;
    float o = bf2[0];
    for (int j = 0; j < 64; j++) {
        float h = bf1[j];
#pragma unroll
        for (int i = 0; i < 32; i++) h += gv[i] * Wf1[i * 64 + j];
        o += fmaxf(h, 0.0f) * Wf2[j];
    }
    out[g] = o;
}

// ---------------- launch ----------------

extern "C" void kernel_launch(void* const* d_in, const int* in_sizes, int n_in,
                              void* d_out, int out_size) {
    const float* x   = (const float*)d_in[0];
    const int* ei    = (const int*)d_in[1];   // int32 (jax x64 disabled)
    const int* batch = (const int*)d_in[2];
    const float* Wq1 = (const float*)d_in[3];
    const float* bq1 = (const float*)d_in[4];
    const float* Wk1 = (const float*)d_in[5];
    const float* bk1 = (const float*)d_in[6];
    const float* Wv1 = (const float*)d_in[7];
    const float* bv1 = (const float*)d_in[8];
    const float* Ws1 = (const float*)d_in[9];
    const float* bs1 = (const float*)d_in[10];
    const float* Wq2 = (const float*)d_in[11];
    const float* bq2 = (const float*)d_in[12];
    const float* Wk2 = (const float*)d_in[13];
    const float* bk2 = (const float*)d_in[14];
    const float* Wv2 = (const float*)d_in[15];
    const float* bv2 = (const float*)d_in[16];
    const float* Ws2 = (const float*)d_in[17];
    const float* bs2 = (const float*)d_in[18];
    const float* Wf1 = (const float*)d_in[19];
    const float* bf1 = (const float*)d_in[20];
    const float* Wf2 = (const float*)d_in[21];
    const float* bf2 = (const float*)d_in[22];
    float* out = (float*)d_out;

    const int* srcp = ei;
    const int* dstp = ei + NE;

    const int EB = (NE + 255) / 256;
    const int NB = (NN + 255) / 256;
    const int WB = (NN * 32 + 255) / 256;  // warp-per-node grids

    // Build CSR (by dst) once; reused by both layers.
    zero_cnt<<<NB, 256>>>();
    hist<<<EB, 256>>>(dstp);
    scan_offsets<<<1, 1024>>>();
    scatter<<<EB, 256>>>(srcp, dstp);

    // Layer 1 (11 -> 16)
    node_transform<11, 16, false><<<NB, 256>>>(x, Wq1, bq1, Wk1, bk1, Wv1, bv1, Ws1, bs1);
    attn_fused<16><<<WB, 256>>>();

    // Layer 2 (16 -> 32)
    node_transform<16, 32, true><<<NB, 256>>>(nullptr, Wq2, bq2, Wk2, bk2, Wv2, bv2, Ws2, bs2);
    attn_fused<32><<<WB, 256>>>();

    // Pool + MLP head
    pool_zero<<<(NG * 32 + 255) / 256, 256>>>();
    pool<<<NB, 256>>>(batch);
    mlp_head<<<(NG + 127) / 128, 128>>>(Wf1, bf1, Wf2, bf2, out);
}